// round 15
// baseline (speedup 1.0000x reference)
#include <cuda_runtime.h>
#include <cuda_fp16.h>
#include <cstdint>
#include <math.h>

#define B_  2
#define H2_ 16
#define H_  8
#define S_  2048
#define D_  128
#define BQ  128
#define BK  64
#define NT  256

// smem layout in __half units
#define KPITCH 136               // 272 B/row; ldmatrix row phase 4r mod 32 -> CF
#define VPITCH 72                // 144 B/row
#define OFF_K  0
#define KSTRIDE (64 * KPITCH)    // 8704 halves per buffer
#define OFF_V  (2 * KSTRIDE)     // 17408
#define VSTRIDE (128 * VPITCH)   // 9216
#define SMH    (OFF_V + 2 * VSTRIDE)  // 35840 halves = 71680 B

// device scratch
__device__ float   g_o[(size_t)B_ * H2_ * S_ * D_];
__device__ __half  g_kh[(size_t)B_ * H2_ * S_ * D_];
__device__ __half  g_vth[(size_t)B_ * H_ * D_ * S_];
__device__ double2 g_part[16 * 64];
__device__ float   g_lam;

__device__ __forceinline__ uint32_t smem_u32(const void* p) {
    uint32_t a;
    asm("{ .reg .u64 t; cvta.to.shared.u64 t, %1; cvt.u32.u64 %0, t; }" : "=r"(a) : "l"(p));
    return a;
}

#define CP16(dst, src) \
    asm volatile("cp.async.cg.shared.global [%0], [%1], 16;" :: "r"(dst), "l"(src))
#define CP_COMMIT() asm volatile("cp.async.commit_group;" ::: "memory")
#define CP_WAIT(n)  asm volatile("cp.async.wait_group %0;" :: "n"(n) : "memory")

#define LDSM4(r0, r1, r2, r3, a) \
    asm volatile("ldmatrix.sync.aligned.m8n8.x4.shared.b16 {%0,%1,%2,%3}, [%4];" \
        : "=r"(r0), "=r"(r1), "=r"(r2), "=r"(r3) : "r"(a))

__device__ __forceinline__ void mma16(float c[4], uint32_t a0, uint32_t a1,
                                      uint32_t a2, uint32_t a3,
                                      uint32_t b0, uint32_t b1) {
    asm volatile(
        "mma.sync.aligned.m16n8k16.row.col.f32.f16.f16.f32 "
        "{%0,%1,%2,%3}, {%4,%5,%6,%7}, {%8,%9}, {%0,%1,%2,%3};"
        : "+f"(c[0]), "+f"(c[1]), "+f"(c[2]), "+f"(c[3])
        : "r"(a0), "r"(a1), "r"(a2), "r"(a3), "r"(b0), "r"(b1));
}

__device__ __forceinline__ uint32_t pack2(float lo, float hi) {
    __half2 h = __floats2half2_rn(lo, hi);
    return *(uint32_t*)&h;
}
__device__ __forceinline__ float ex2f(float x) {
    float r;
    asm("ex2.approx.f32 %0, %1;" : "=f"(r) : "f"(x));
    return r;
}

// ---------------------------------------------------------------------------
// k fp32 -> fp16, same layout
__global__ void cvt_kernel(const float4* __restrict__ k, uint2* __restrict__ kh) {
    int i = blockIdx.x * blockDim.x + threadIdx.x;
    float4 v = k[i];
    uint2 o;
    o.x = pack2(v.x, v.y);
    o.y = pack2(v.z, v.w);
    kh[i] = o;
}

// v[bh][s][d] fp32 -> g_vth[bh][d][s] fp16, 64s x 32d tiles, half2 stores.
// block (0,0,0) also computes lambda.
__global__ void vtr_kernel(const float* __restrict__ v,
                           const float* __restrict__ lq1, const float* __restrict__ lk1,
                           const float* __restrict__ lq2, const float* __restrict__ lk2) {
    __shared__ __half st[32][66];
    __shared__ float lr1[4], lr2[4];
    const int tid = threadIdx.x;  // 256 threads
    int sbase = blockIdx.x * 64, dbase = blockIdx.y * 32, bh = blockIdx.z;
    const float* src = v + (size_t)bh * S_ * D_;
    __half* dst = g_vth + (size_t)bh * (size_t)D_ * S_;

    #pragma unroll
    for (int i = 0; i < 8; i++) {
        int idx = tid + i * 256;
        int s = idx >> 5, d = idx & 31;
        st[d][s] = __float2half(src[(size_t)(sbase + s) * D_ + dbase + d]);
    }
    __syncthreads();
    #pragma unroll
    for (int i = 0; i < 4; i++) {
        int idx = tid + i * 256;
        int d = idx >> 5, x = idx & 31;
        *(__half2*)(dst + (size_t)(dbase + d) * S_ + sbase + 2 * x) =
            *(const __half2*)&st[d][2 * x];
    }

    if (blockIdx.x == 0 && blockIdx.y == 0 && blockIdx.z == 0) {
        if (tid < 128) {
            float v1 = lq1[tid] * lk1[tid];
            float v2 = lq2[tid] * lk2[tid];
            #pragma unroll
            for (int o = 16; o; o >>= 1) {
                v1 += __shfl_xor_sync(0xffffffffu, v1, o);
                v2 += __shfl_xor_sync(0xffffffffu, v2, o);
            }
            if ((tid & 31) == 0) { lr1[tid >> 5] = v1; lr2[tid >> 5] = v2; }
        }
        __syncthreads();
        if (tid == 0) {
            float a = lr1[0] + lr1[1] + lr1[2] + lr1[3];
            float b = lr2[0] + lr2[1] + lr2[2] + lr2[3];
            g_lam = expf(a) - expf(b) + 0.8f;
        }
    }
}

// ---------------------------------------------------------------------------
// fp16 mma flash attention with ghostmax. Scores in log2 domain (log2e folded
// into Q scale) -> bare ex2.approx; warp-uniform unmasked fast path.
// ---------------------------------------------------------------------------
__global__ __launch_bounds__(NT, 1)
void attn_kernel(const float* __restrict__ q) {
    extern __shared__ __half smh[];
    const uint32_t sb = smem_u32(smh);
    const int tid = threadIdx.x, lane = tid & 31, warp = tid >> 5;
    const int g = lane >> 2, t = lane & 3;
    const int qt = (int)gridDim.x - 1 - (int)blockIdx.x;  // heavy tiles first
    const int h2 = blockIdx.y, b = blockIdx.z;
    const int qbase = qt * BQ;
    const int row_lo = qbase + warp * 16 + g;
    const int row_hi = row_lo + 8;
    const int rowmin = qbase + warp * 16;
    const int rowmax = rowmin + 15;
    const size_t baseQ  = ((size_t)b * H2_ + h2) * S_ * D_;
    const size_t baseVT = ((size_t)b * H_ + (h2 >> 1)) * (size_t)D_ * S_;
    // 1/sqrt(128) * log2(e): scores come out in log2 domain
    const float scaling = 0.12751743329705586f;

    const int rowsel = (lane & 7) + ((lane >> 4) << 3);
    const uint32_t koff = ((lane >> 3) & 1) * 16;

    // ---- Q A-fragments: convert from fp32 once into registers
    uint32_t aq[8][4];
    {
        const float* Qlo = q + baseQ + (size_t)row_lo * D_;
        const float* Qhi = q + baseQ + (size_t)row_hi * D_;
        #pragma unroll
        for (int ks = 0; ks < 8; ks++) {
            float2 v0 = *(const float2*)(Qlo + ks * 16 + 2 * t);
            float2 v1 = *(const float2*)(Qhi + ks * 16 + 2 * t);
            float2 v2 = *(const float2*)(Qlo + ks * 16 + 2 * t + 8);
            float2 v3 = *(const float2*)(Qhi + ks * 16 + 2 * t + 8);
            aq[ks][0] = pack2(v0.x * scaling, v0.y * scaling);
            aq[ks][1] = pack2(v1.x * scaling, v1.y * scaling);
            aq[ks][2] = pack2(v2.x * scaling, v2.y * scaling);
            aq[ks][3] = pack2(v3.x * scaling, v3.y * scaling);
        }
    }

    const int nsteps = 2 * (qt + 1);

    auto issue = [&](int jt, int buf) {
        const __half* ksrc = g_kh + baseQ + (size_t)jt * BK * D_;
        uint32_t kdst = sb + (OFF_K + buf * KSTRIDE) * 2;
        #pragma unroll
        for (int i = 0; i < 4; i++) {
            int idx = tid + i * NT;
            int r = idx >> 4, c = idx & 15;
            CP16(kdst + r * 272 + c * 16, ksrc + r * 128 + c * 8);
        }
        const __half* vsrc = g_vth + baseVT + jt * BK;
        uint32_t vdst = sb + (OFF_V + buf * VSTRIDE) * 2;
        #pragma unroll
        for (int i = 0; i < 4; i++) {
            int idx = tid + i * NT;
            int r = idx >> 3, c = idx & 7;
            CP16(vdst + r * 144 + c * 16, vsrc + (size_t)r * S_ + c * 8);
        }
        CP_COMMIT();
    };

    issue(0, 0);

    float o[16][4];
    #pragma unroll
    for (int i = 0; i < 16; i++)
        #pragma unroll
        for (int j = 0; j < 4; j++) o[i][j] = 0.0f;
    float l_lo = 0.0f, l_hi = 0.0f;

    for (int jt = 0; jt < nsteps; ++jt) {
        const int buf = jt & 1;
        __syncthreads();
        if (jt + 1 < nsteps) {
            issue(jt + 1, buf ^ 1);
            CP_WAIT(1);
        } else {
            CP_WAIT(0);
        }
        __syncthreads();

        if (jt * BK <= rowmax) {
            // ---- GEMM1: S = Q @ K^T (log2 domain)
            float s[8][4];
            #pragma unroll
            for (int i = 0; i < 8; i++)
                #pragma unroll
                for (int j = 0; j < 4; j++) s[i][j] = 0.0f;

            const uint32_t kmb = sb + (OFF_K + buf * KSTRIDE) * 2 + rowsel * 272 + koff;
            #pragma unroll
            for (int ks = 0; ks < 8; ks++) {
                #pragma unroll
                for (int np = 0; np < 4; np++) {
                    uint32_t b0, b1, b2, b3;
                    LDSM4(b0, b1, b2, b3, kmb + np * (16 * 272) + ks * 32);
                    mma16(s[2 * np],     aq[ks][0], aq[ks][1], aq[ks][2], aq[ks][3], b0, b1);
                    mma16(s[2 * np + 1], aq[ks][0], aq[ks][1], aq[ks][2], aq[ks][3], b2, b3);
                }
            }

            // ---- ghostmax numerators: p = exp2(s); mask only near diagonal
            if (jt * BK + (BK - 1) <= rowmin) {  // fully unmasked step
                #pragma unroll
                for (int nt = 0; nt < 8; nt++) {
                    float p0 = ex2f(s[nt][0]);
                    float p1 = ex2f(s[nt][1]);
                    float p2 = ex2f(s[nt][2]);
                    float p3 = ex2f(s[nt][3]);
                    s[nt][0] = p0; s[nt][1] = p1; s[nt][2] = p2; s[nt][3] = p3;
                    l_lo += p0 + p1;
                    l_hi += p2 + p3;
                }
            } else {
                #pragma unroll
                for (int nt = 0; nt < 8; nt++) {
                    int c0 = jt * BK + nt * 8 + 2 * t;
                    float p0 = (c0     <= row_lo) ? ex2f(s[nt][0]) : 0.0f;
                    float p1 = (c0 + 1 <= row_lo) ? ex2f(s[nt][1]) : 0.0f;
                    float p2 = (c0     <= row_hi) ? ex2f(s[nt][2]) : 0.0f;
                    float p3 = (c0 + 1 <= row_hi) ? ex2f(s[nt][3]) : 0.0f;
                    s[nt][0] = p0; s[nt][1] = p1; s[nt][2] = p2; s[nt][3] = p3;
                    l_lo += p0 + p1;
                    l_hi += p2 + p3;
                }
            }

            // ---- GEMM2: O += P @ V (C-frags feed A-frags directly)
            const uint32_t vmb = sb + (OFF_V + buf * VSTRIDE) * 2 + rowsel * 144 + koff;
            #pragma unroll
            for (int j2 = 0; j2 < 4; j2++) {
                uint32_t a0 = pack2(s[2 * j2][0],     s[2 * j2][1]);
                uint32_t a1 = pack2(s[2 * j2][2],     s[2 * j2][3]);
                uint32_t a2 = pack2(s[2 * j2 + 1][0], s[2 * j2 + 1][1]);
                uint32_t a3 = pack2(s[2 * j2 + 1][2], s[2 * j2 + 1][3]);
                #pragma unroll
                for (int np = 0; np < 8; np++) {
                    uint32_t b0, b1, b2, b3;
                    LDSM4(b0, b1, b2, b3, vmb + np * (16 * 144) + j2 * 32);
                    mma16(o[2 * np],     a0, a1, a2, a3, b0, b1);
                    mma16(o[2 * np + 1], a0, a1, a2, a3, b2, b3);
                }
            }
        }
    }

    // reduce l across quad, normalize, store
    l_lo += __shfl_xor_sync(0xffffffffu, l_lo, 1);
    l_lo += __shfl_xor_sync(0xffffffffu, l_lo, 2);
    l_hi += __shfl_xor_sync(0xffffffffu, l_hi, 1);
    l_hi += __shfl_xor_sync(0xffffffffu, l_hi, 2);
    const float inv_lo = 1.0f / (l_lo + 1.0f);
    const float inv_hi = 1.0f / (l_hi + 1.0f);

    float* olo = g_o + baseQ + (size_t)row_lo * D_;
    float* ohi = g_o + baseQ + (size_t)row_hi * D_;
    #pragma unroll
    for (int nt = 0; nt < 16; nt++) {
        int c = nt * 8 + 2 * t;
        *(float2*)(olo + c) = make_float2(o[nt][0] * inv_lo, o[nt][1] * inv_lo);
        *(float2*)(ohi + c) = make_float2(o[nt][2] * inv_hi, o[nt][3] * inv_hi);
    }
}

// ---------------------------------------------------------------------------
// GroupNorm stats over x = o1 - lam*o2 per (b,h).
// ---------------------------------------------------------------------------
__global__ void gn_partial() {
    const int slice = blockIdx.x;   // 0..63
    const int bh = blockIdx.y;      // 0..15
    const int b = bh >> 3, h = bh & 7;
    const float lam = g_lam;
    const float4* o1 = (const float4*)(g_o + ((size_t)b * H2_ + 2 * h) * S_ * D_);
    const float4* o2 = o1 + (size_t)S_ * D_ / 4;
    float s = 0.0f, s2 = 0.0f;
    #pragma unroll
    for (int i = 0; i < 4; i++) {
        int idx = slice * 1024 + threadIdx.x + i * 256;
        float4 a = o1[idx], c = o2[idx];
        float x0 = a.x - lam * c.x, x1 = a.y - lam * c.y;
        float x2 = a.z - lam * c.z, x3 = a.w - lam * c.w;
        s += x0 + x1 + x2 + x3;
        s2 = fmaf(x0, x0, s2); s2 = fmaf(x1, x1, s2);
        s2 = fmaf(x2, x2, s2); s2 = fmaf(x3, x3, s2);
    }
    #pragma unroll
    for (int o = 16; o; o >>= 1) {
        s  += __shfl_xor_sync(0xffffffffu, s, o);
        s2 += __shfl_xor_sync(0xffffffffu, s2, o);
    }
    __shared__ double rs[8], rs2[8];
    if ((threadIdx.x & 31) == 0) {
        rs[threadIdx.x >> 5] = (double)s;
        rs2[threadIdx.x >> 5] = (double)s2;
    }
    __syncthreads();
    if (threadIdx.x == 0) {
        double a = 0.0, c = 0.0;
        #pragma unroll
        for (int i = 0; i < 8; i++) { a += rs[i]; c += rs2[i]; }
        g_part[bh * 64 + slice] = make_double2(a, c);
    }
}

// finalize (64-slice reduce of g_part) fused into apply; 512 threads/block
__global__ void gn_apply(const float* __restrict__ gw, const float* __restrict__ gb,
                         float* __restrict__ out) {
    __shared__ float2 stsh;
    const size_t e0 = (size_t)blockIdx.x * 2048;
    {
        int c_ = (int)((e0 >> 11) & 1023);
        int bh = ((int)(e0 >> 21)) * 8 + (c_ >> 7);
        if (threadIdx.x < 32) {
            double2 p0 = g_part[bh * 64 + threadIdx.x];
            double2 p1 = g_part[bh * 64 + threadIdx.x + 32];
            double s = p0.x + p1.x, s2 = p0.y + p1.y;
            #pragma unroll
            for (int o = 16; o; o >>= 1) {
                s  += __shfl_xor_sync(0xffffffffu, s, o);
                s2 += __shfl_xor_sync(0xffffffffu, s2, o);
            }
            if (threadIdx.x == 0) {
                const double N = (double)S_ * D_;
                double mean = s / N;
                double var = s2 / N - mean * mean;
                stsh = make_float2((float)mean, (float)(1.0 / sqrt(var + 1e-5)));
            }
        }
    }
    __syncthreads();
    float2 st = stsh;
    size_t e = e0 + (size_t)threadIdx.x * 4;
    int t = (int)(e & 2047);
    int c = (int)((e >> 11) & 1023);
    int b = (int)(e >> 21);
    int h = c >> 7, cl = c & 127;
    int s = cl * 16 + (t >> 7), d = t & 127;
    const float lam = g_lam;
    size_t off = (((size_t)b * H2_ + 2 * h) * S_ + s) * D_ + d;
    float4 a = *(const float4*)(g_o + off);
    float4 cc = *(const float4*)(g_o + off + (size_t)S_ * D_);
    float wgt = 0.2f * st.y * gw[c];
    float bias = 0.2f * (gb[c] - st.x * st.y * gw[c]);
    float4 r;
    r.x = (a.x - lam * cc.x) * wgt + bias;
    r.y = (a.y - lam * cc.y) * wgt + bias;
    r.z = (a.z - lam * cc.z) * wgt + bias;
    r.w = (a.w - lam * cc.w) * wgt + bias;
    *(float4*)(out + e) = r;
}

// ---------------------------------------------------------------------------
extern "C" void kernel_launch(void* const* d_in, const int* in_sizes, int n_in,
                              void* d_out, int out_size) {
    const float* q   = (const float*)d_in[0];
    const float* k   = (const float*)d_in[1];
    const float* v   = (const float*)d_in[2];
    const float* lq1 = (const float*)d_in[3];
    const float* lk1 = (const float*)d_in[4];
    const float* lq2 = (const float*)d_in[5];
    const float* lk2 = (const float*)d_in[6];
    const float* gw  = (const float*)d_in[7];
    const float* gb  = (const float*)d_in[8];
    float* out = (float*)d_out;

    const int smem = SMH * 2;  // 71680 B
    cudaFuncSetAttribute(attn_kernel, cudaFuncAttributeMaxDynamicSharedMemorySize, smem);

    __half* kh; cudaGetSymbolAddress((void**)&kh, g_kh);

    cvt_kernel<<<8192, 256>>>((const float4*)k, (uint2*)kh);
    vtr_kernel<<<dim3(S_ / 64, D_ / 32, B_ * H_), 256>>>(v, lq1, lk1, lq2, lk2);
    attn_kernel<<<dim3(S_ / BQ, H2_, B_), NT, smem>>>(q);
    gn_partial<<<dim3(64, 16), 256>>>();
    gn_apply<<<2048, 512>>>(gw, gb, out);
}

// round 16
// speedup vs baseline: 1.0427x; 1.0427x over previous
#include <cuda_runtime.h>
#include <cuda_fp16.h>
#include <cstdint>
#include <math.h>

#define B_  2
#define H2_ 16
#define H_  8
#define S_  2048
#define D_  128
#define BQ  128
#define BK  64
#define NT  256

// smem layout in __half units
#define KPITCH 136               // 272 B/row; ldmatrix row phase 4r mod 32 -> CF
#define VPITCH 72                // 144 B/row
#define OFF_K  0
#define KSTRIDE (64 * KPITCH)    // 8704 halves per buffer
#define OFF_V  (2 * KSTRIDE)     // 17408
#define VSTRIDE (128 * VPITCH)   // 9216
#define SMH    (OFF_V + 2 * VSTRIDE)  // 35840 halves = 71680 B

// device scratch
__device__ __half  g_oh[(size_t)B_ * H2_ * S_ * D_];
__device__ __half  g_kh[(size_t)B_ * H2_ * S_ * D_];
__device__ __half  g_vth[(size_t)B_ * H_ * D_ * S_];
__device__ double2 g_part[16 * 64];
__device__ float   g_lam;

__device__ __forceinline__ uint32_t smem_u32(const void* p) {
    uint32_t a;
    asm("{ .reg .u64 t; cvta.to.shared.u64 t, %1; cvt.u32.u64 %0, t; }" : "=r"(a) : "l"(p));
    return a;
}

#define CP16(dst, src) \
    asm volatile("cp.async.cg.shared.global [%0], [%1], 16;" :: "r"(dst), "l"(src))
#define CP_COMMIT() asm volatile("cp.async.commit_group;" ::: "memory")
#define CP_WAIT(n)  asm volatile("cp.async.wait_group %0;" :: "n"(n) : "memory")

#define LDSM4(r0, r1, r2, r3, a) \
    asm volatile("ldmatrix.sync.aligned.m8n8.x4.shared.b16 {%0,%1,%2,%3}, [%4];" \
        : "=r"(r0), "=r"(r1), "=r"(r2), "=r"(r3) : "r"(a))

__device__ __forceinline__ void mma16(float c[4], uint32_t a0, uint32_t a1,
                                      uint32_t a2, uint32_t a3,
                                      uint32_t b0, uint32_t b1) {
    asm volatile(
        "mma.sync.aligned.m16n8k16.row.col.f32.f16.f16.f32 "
        "{%0,%1,%2,%3}, {%4,%5,%6,%7}, {%8,%9}, {%0,%1,%2,%3};"
        : "+f"(c[0]), "+f"(c[1]), "+f"(c[2]), "+f"(c[3])
        : "r"(a0), "r"(a1), "r"(a2), "r"(a3), "r"(b0), "r"(b1));
}

__device__ __forceinline__ uint32_t pack2(float lo, float hi) {
    __half2 h = __floats2half2_rn(lo, hi);
    return *(uint32_t*)&h;
}

// ---------------------------------------------------------------------------
// k fp32 -> fp16, same layout
__global__ void cvt_kernel(const float4* __restrict__ k, uint2* __restrict__ kh) {
    int i = blockIdx.x * blockDim.x + threadIdx.x;
    float4 v = k[i];
    uint2 o;
    o.x = pack2(v.x, v.y);
    o.y = pack2(v.z, v.w);
    kh[i] = o;
}

// v[bh][s][d] fp32 -> g_vth[bh][d][s] fp16, 64s x 32d tiles, half2 stores.
// block (0,0,0) also computes lambda.
__global__ void vtr_kernel(const float* __restrict__ v,
                           const float* __restrict__ lq1, const float* __restrict__ lk1,
                           const float* __restrict__ lq2, const float* __restrict__ lk2) {
    __shared__ __half st[32][66];
    __shared__ float lr1[4], lr2[4];
    const int tid = threadIdx.x;  // 256 threads
    int sbase = blockIdx.x * 64, dbase = blockIdx.y * 32, bh = blockIdx.z;
    const float* src = v + (size_t)bh * S_ * D_;
    __half* dst = g_vth + (size_t)bh * (size_t)D_ * S_;

    #pragma unroll
    for (int i = 0; i < 8; i++) {
        int idx = tid + i * 256;
        int s = idx >> 5, d = idx & 31;
        st[d][s] = __float2half(src[(size_t)(sbase + s) * D_ + dbase + d]);
    }
    __syncthreads();
    #pragma unroll
    for (int i = 0; i < 4; i++) {
        int idx = tid + i * 256;
        int d = idx >> 5, x = idx & 31;
        *(__half2*)(dst + (size_t)(dbase + d) * S_ + sbase + 2 * x) =
            *(const __half2*)&st[d][2 * x];
    }

    if (blockIdx.x == 0 && blockIdx.y == 0 && blockIdx.z == 0) {
        if (tid < 128) {
            float v1 = lq1[tid] * lk1[tid];
            float v2 = lq2[tid] * lk2[tid];
            #pragma unroll
            for (int o = 16; o; o >>= 1) {
                v1 += __shfl_xor_sync(0xffffffffu, v1, o);
                v2 += __shfl_xor_sync(0xffffffffu, v2, o);
            }
            if ((tid & 31) == 0) { lr1[tid >> 5] = v1; lr2[tid >> 5] = v2; }
        }
        __syncthreads();
        if (tid == 0) {
            float a = lr1[0] + lr1[1] + lr1[2] + lr1[3];
            float b = lr2[0] + lr2[1] + lr2[2] + lr2[3];
            g_lam = expf(a) - expf(b) + 0.8f;
        }
    }
}

// ---------------------------------------------------------------------------
// fp16 mma flash attention with ghostmax (R14/R6 configuration, frozen).
// Output stored fp16 to halve epilogue traffic.
// ---------------------------------------------------------------------------
__global__ __launch_bounds__(NT, 1)
void attn_kernel(const float* __restrict__ q) {
    extern __shared__ __half smh[];
    const uint32_t sb = smem_u32(smh);
    const int tid = threadIdx.x, lane = tid & 31, warp = tid >> 5;
    const int g = lane >> 2, t = lane & 3;
    const int qt = (int)gridDim.x - 1 - (int)blockIdx.x;  // heavy tiles first
    const int h2 = blockIdx.y, b = blockIdx.z;
    const int qbase = qt * BQ;
    const int row_lo = qbase + warp * 16 + g;
    const int row_hi = row_lo + 8;
    const int rowmax = qbase + warp * 16 + 15;
    const size_t baseQ  = ((size_t)b * H2_ + h2) * S_ * D_;
    const size_t baseVT = ((size_t)b * H_ + (h2 >> 1)) * (size_t)D_ * S_;
    const float scaling = 0.08838834764831845f;

    const int rowsel = (lane & 7) + ((lane >> 4) << 3);
    const uint32_t koff = ((lane >> 3) & 1) * 16;

    // ---- Q A-fragments: convert from fp32 once into registers
    uint32_t aq[8][4];
    {
        const float* Qlo = q + baseQ + (size_t)row_lo * D_;
        const float* Qhi = q + baseQ + (size_t)row_hi * D_;
        #pragma unroll
        for (int ks = 0; ks < 8; ks++) {
            float2 v0 = *(const float2*)(Qlo + ks * 16 + 2 * t);
            float2 v1 = *(const float2*)(Qhi + ks * 16 + 2 * t);
            float2 v2 = *(const float2*)(Qlo + ks * 16 + 2 * t + 8);
            float2 v3 = *(const float2*)(Qhi + ks * 16 + 2 * t + 8);
            aq[ks][0] = pack2(v0.x * scaling, v0.y * scaling);
            aq[ks][1] = pack2(v1.x * scaling, v1.y * scaling);
            aq[ks][2] = pack2(v2.x * scaling, v2.y * scaling);
            aq[ks][3] = pack2(v3.x * scaling, v3.y * scaling);
        }
    }

    const int nsteps = 2 * (qt + 1);

    auto issue = [&](int jt, int buf) {
        const __half* ksrc = g_kh + baseQ + (size_t)jt * BK * D_;
        uint32_t kdst = sb + (OFF_K + buf * KSTRIDE) * 2;
        #pragma unroll
        for (int i = 0; i < 4; i++) {
            int idx = tid + i * NT;
            int r = idx >> 4, c = idx & 15;
            CP16(kdst + r * 272 + c * 16, ksrc + r * 128 + c * 8);
        }
        const __half* vsrc = g_vth + baseVT + jt * BK;
        uint32_t vdst = sb + (OFF_V + buf * VSTRIDE) * 2;
        #pragma unroll
        for (int i = 0; i < 4; i++) {
            int idx = tid + i * NT;
            int r = idx >> 3, c = idx & 7;
            CP16(vdst + r * 144 + c * 16, vsrc + (size_t)r * S_ + c * 8);
        }
        CP_COMMIT();
    };

    issue(0, 0);

    float o[16][4];
    #pragma unroll
    for (int i = 0; i < 16; i++)
        #pragma unroll
        for (int j = 0; j < 4; j++) o[i][j] = 0.0f;
    float l_lo = 0.0f, l_hi = 0.0f;

    for (int jt = 0; jt < nsteps; ++jt) {
        const int buf = jt & 1;
        __syncthreads();
        if (jt + 1 < nsteps) {
            issue(jt + 1, buf ^ 1);
            CP_WAIT(1);
        } else {
            CP_WAIT(0);
        }
        __syncthreads();

        if (jt * BK <= rowmax) {
            // ---- GEMM1: S = Q @ K^T
            float s[8][4];
            #pragma unroll
            for (int i = 0; i < 8; i++)
                #pragma unroll
                for (int j = 0; j < 4; j++) s[i][j] = 0.0f;

            const uint32_t kmb = sb + (OFF_K + buf * KSTRIDE) * 2 + rowsel * 272 + koff;
            #pragma unroll
            for (int ks = 0; ks < 8; ks++) {
                #pragma unroll
                for (int np = 0; np < 4; np++) {
                    uint32_t b0, b1, b2, b3;
                    LDSM4(b0, b1, b2, b3, kmb + np * (16 * 272) + ks * 32);
                    mma16(s[2 * np],     aq[ks][0], aq[ks][1], aq[ks][2], aq[ks][3], b0, b1);
                    mma16(s[2 * np + 1], aq[ks][0], aq[ks][1], aq[ks][2], aq[ks][3], b2, b3);
                }
            }

            // ---- ghostmax numerators + causal mask + row sums
            #pragma unroll
            for (int nt = 0; nt < 8; nt++) {
                int c0 = jt * BK + nt * 8 + 2 * t;
                float p0 = (c0     <= row_lo) ? __expf(s[nt][0]) : 0.0f;
                float p1 = (c0 + 1 <= row_lo) ? __expf(s[nt][1]) : 0.0f;
                float p2 = (c0     <= row_hi) ? __expf(s[nt][2]) : 0.0f;
                float p3 = (c0 + 1 <= row_hi) ? __expf(s[nt][3]) : 0.0f;
                s[nt][0] = p0; s[nt][1] = p1; s[nt][2] = p2; s[nt][3] = p3;
                l_lo += p0 + p1;
                l_hi += p2 + p3;
            }

            // ---- GEMM2: O += P @ V (C-frags feed A-frags directly)
            const uint32_t vmb = sb + (OFF_V + buf * VSTRIDE) * 2 + rowsel * 144 + koff;
            #pragma unroll
            for (int j2 = 0; j2 < 4; j2++) {
                uint32_t a0 = pack2(s[2 * j2][0],     s[2 * j2][1]);
                uint32_t a1 = pack2(s[2 * j2][2],     s[2 * j2][3]);
                uint32_t a2 = pack2(s[2 * j2 + 1][0], s[2 * j2 + 1][1]);
                uint32_t a3 = pack2(s[2 * j2 + 1][2], s[2 * j2 + 1][3]);
                #pragma unroll
                for (int np = 0; np < 8; np++) {
                    uint32_t b0, b1, b2, b3;
                    LDSM4(b0, b1, b2, b3, vmb + np * (16 * 144) + j2 * 32);
                    mma16(o[2 * np],     a0, a1, a2, a3, b0, b1);
                    mma16(o[2 * np + 1], a0, a1, a2, a3, b2, b3);
                }
            }
        }
    }

    // reduce l across quad, normalize, store fp16
    l_lo += __shfl_xor_sync(0xffffffffu, l_lo, 1);
    l_lo += __shfl_xor_sync(0xffffffffu, l_lo, 2);
    l_hi += __shfl_xor_sync(0xffffffffu, l_hi, 1);
    l_hi += __shfl_xor_sync(0xffffffffu, l_hi, 2);
    const float inv_lo = 1.0f / (l_lo + 1.0f);
    const float inv_hi = 1.0f / (l_hi + 1.0f);

    __half* olo = g_oh + baseQ + (size_t)row_lo * D_;
    __half* ohi = g_oh + baseQ + (size_t)row_hi * D_;
    #pragma unroll
    for (int nt = 0; nt < 16; nt++) {
        int c = nt * 8 + 2 * t;
        *(uint32_t*)(olo + c) = pack2(o[nt][0] * inv_lo, o[nt][1] * inv_lo);
        *(uint32_t*)(ohi + c) = pack2(o[nt][2] * inv_hi, o[nt][3] * inv_hi);
    }
}

// ---------------------------------------------------------------------------
// GroupNorm stats over x = o1 - lam*o2 per (b,h), fp16 input.
// ---------------------------------------------------------------------------
__global__ void gn_partial() {
    const int slice = blockIdx.x;   // 0..63
    const int bh = blockIdx.y;      // 0..15
    const int b = bh >> 3, h = bh & 7;
    const float lam = g_lam;
    const uint4* o1 = (const uint4*)(g_oh + ((size_t)b * H2_ + 2 * h) * S_ * D_);
    const uint4* o2 = o1 + (size_t)S_ * D_ / 8;
    float s = 0.0f, s2 = 0.0f;
    #pragma unroll
    for (int i = 0; i < 2; i++) {
        int idx = slice * 512 + threadIdx.x + i * 256;
        uint4 ua = o1[idx], uc = o2[idx];
        #pragma unroll
        for (int w = 0; w < 4; w++) {
            uint32_t wa = (&ua.x)[w], wc = (&uc.x)[w];
            float2 fa = __half22float2(*(const __half2*)&wa);
            float2 fc = __half22float2(*(const __half2*)&wc);
            float x0 = fa.x - lam * fc.x;
            float x1 = fa.y - lam * fc.y;
            s += x0 + x1;
            s2 = fmaf(x0, x0, s2);
            s2 = fmaf(x1, x1, s2);
        }
    }
    #pragma unroll
    for (int o = 16; o; o >>= 1) {
        s  += __shfl_xor_sync(0xffffffffu, s, o);
        s2 += __shfl_xor_sync(0xffffffffu, s2, o);
    }
    __shared__ double rs[8], rs2[8];
    if ((threadIdx.x & 31) == 0) {
        rs[threadIdx.x >> 5] = (double)s;
        rs2[threadIdx.x >> 5] = (double)s2;
    }
    __syncthreads();
    if (threadIdx.x == 0) {
        double a = 0.0, c = 0.0;
        #pragma unroll
        for (int i = 0; i < 8; i++) { a += rs[i]; c += rs2[i]; }
        g_part[bh * 64 + slice] = make_double2(a, c);
    }
}

// finalize (64-slice reduce of g_part) fused into apply; fp16 input
__global__ void gn_apply(const float* __restrict__ gw, const float* __restrict__ gb,
                         float* __restrict__ out) {
    __shared__ float2 stsh;
    const size_t e0 = (size_t)blockIdx.x * 1024;
    {
        int c_ = (int)((e0 >> 11) & 1023);
        int bh = ((int)(e0 >> 21)) * 8 + (c_ >> 7);
        if (threadIdx.x < 32) {
            double2 p0 = g_part[bh * 64 + threadIdx.x];
            double2 p1 = g_part[bh * 64 + threadIdx.x + 32];
            double s = p0.x + p1.x, s2 = p0.y + p1.y;
            #pragma unroll
            for (int o = 16; o; o >>= 1) {
                s  += __shfl_xor_sync(0xffffffffu, s, o);
                s2 += __shfl_xor_sync(0xffffffffu, s2, o);
            }
            if (threadIdx.x == 0) {
                const double N = (double)S_ * D_;
                double mean = s / N;
                double var = s2 / N - mean * mean;
                stsh = make_float2((float)mean, (float)(1.0 / sqrt(var + 1e-5)));
            }
        }
    }
    __syncthreads();
    float2 st = stsh;
    size_t e = e0 + (size_t)threadIdx.x * 4;
    int t = (int)(e & 2047);
    int c = (int)((e >> 11) & 1023);
    int b = (int)(e >> 21);
    int h = c >> 7, cl = c & 127;
    int s = cl * 16 + (t >> 7), d = t & 127;
    const float lam = g_lam;
    size_t off = (((size_t)b * H2_ + 2 * h) * S_ + s) * D_ + d;
    uint2 ua = *(const uint2*)(g_oh + off);
    uint2 uc = *(const uint2*)(g_oh + off + (size_t)S_ * D_);
    float2 a0 = __half22float2(*(const __half2*)&ua.x);
    float2 a1 = __half22float2(*(const __half2*)&ua.y);
    float2 c0 = __half22float2(*(const __half2*)&uc.x);
    float2 c1 = __half22float2(*(const __half2*)&uc.y);
    float wgt = 0.2f * st.y * gw[c];
    float bias = 0.2f * (gb[c] - st.x * st.y * gw[c]);
    float4 r;
    r.x = (a0.x - lam * c0.x) * wgt + bias;
    r.y = (a0.y - lam * c0.y) * wgt + bias;
    r.z = (a1.x - lam * c1.x) * wgt + bias;
    r.w = (a1.y - lam * c1.y) * wgt + bias;
    *(float4*)(out + e) = r;
}

// ---------------------------------------------------------------------------
extern "C" void kernel_launch(void* const* d_in, const int* in_sizes, int n_in,
                              void* d_out, int out_size) {
    const float* q   = (const float*)d_in[0];
    const float* k   = (const float*)d_in[1];
    const float* v   = (const float*)d_in[2];
    const float* lq1 = (const float*)d_in[3];
    const float* lk1 = (const float*)d_in[4];
    const float* lq2 = (const float*)d_in[5];
    const float* lk2 = (const float*)d_in[6];
    const float* gw  = (const float*)d_in[7];
    const float* gb  = (const float*)d_in[8];
    float* out = (float*)d_out;

    const int smem = SMH * 2;  // 71680 B
    cudaFuncSetAttribute(attn_kernel, cudaFuncAttributeMaxDynamicSharedMemorySize, smem);

    __half* kh; cudaGetSymbolAddress((void**)&kh, g_kh);

    cvt_kernel<<<8192, 256>>>((const float4*)k, (uint2*)kh);
    vtr_kernel<<<dim3(S_ / 64, D_ / 32, B_ * H_), 256>>>(v, lq1, lk1, lq2, lk2);
    attn_kernel<<<dim3(S_ / BQ, H2_, B_), NT, smem>>>(q);
    gn_partial<<<dim3(64, 16), 256>>>();
    gn_apply<<<4096, 256>>>(gw, gb, out);
}

// round 17
// speedup vs baseline: 1.0849x; 1.0404x over previous
#include <cuda_runtime.h>
#include <cuda_fp16.h>
#include <cstdint>
#include <math.h>

#define B_  2
#define H2_ 16
#define H_  8
#define S_  2048
#define D_  128
#define BQ  128
#define BK  64
#define NT  256

// smem layout in __half units
#define KPITCH 136               // 272 B/row; ldmatrix row phase 4r mod 32 -> CF
#define VPITCH 72                // 144 B/row
#define OFF_K  0
#define KSTRIDE (64 * KPITCH)    // 8704 halves per buffer
#define OFF_V  (2 * KSTRIDE)     // 17408
#define VSTRIDE (128 * VPITCH)   // 9216
#define SMH    (OFF_V + 2 * VSTRIDE)  // 35840 halves = 71680 B

// device scratch
__device__ __half  g_oh[(size_t)B_ * H2_ * S_ * D_];
__device__ __half  g_kh[(size_t)B_ * H2_ * S_ * D_];
__device__ __half  g_vth[(size_t)B_ * H_ * D_ * S_];
__device__ double2 g_part[16 * 64];
__device__ float   g_lam;

__device__ __forceinline__ uint32_t smem_u32(const void* p) {
    uint32_t a;
    asm("{ .reg .u64 t; cvta.to.shared.u64 t, %1; cvt.u32.u64 %0, t; }" : "=r"(a) : "l"(p));
    return a;
}

#define CP16(dst, src) \
    asm volatile("cp.async.cg.shared.global [%0], [%1], 16;" :: "r"(dst), "l"(src))
#define CP_COMMIT() asm volatile("cp.async.commit_group;" ::: "memory")
#define CP_WAIT(n)  asm volatile("cp.async.wait_group %0;" :: "n"(n) : "memory")

#define LDSM4(r0, r1, r2, r3, a) \
    asm volatile("ldmatrix.sync.aligned.m8n8.x4.shared.b16 {%0,%1,%2,%3}, [%4];" \
        : "=r"(r0), "=r"(r1), "=r"(r2), "=r"(r3) : "r"(a))

__device__ __forceinline__ void mma16(float c[4], uint32_t a0, uint32_t a1,
                                      uint32_t a2, uint32_t a3,
                                      uint32_t b0, uint32_t b1) {
    asm volatile(
        "mma.sync.aligned.m16n8k16.row.col.f32.f16.f16.f32 "
        "{%0,%1,%2,%3}, {%4,%5,%6,%7}, {%8,%9}, {%0,%1,%2,%3};"
        : "+f"(c[0]), "+f"(c[1]), "+f"(c[2]), "+f"(c[3])
        : "r"(a0), "r"(a1), "r"(a2), "r"(a3), "r"(b0), "r"(b1));
}

__device__ __forceinline__ uint32_t pack2(float lo, float hi) {
    __half2 h = __floats2half2_rn(lo, hi);
    return *(uint32_t*)&h;
}

// ---------------------------------------------------------------------------
// Fused prepass: y<4 -> V transpose tile; y==4 -> K fp32->fp16 chunk.
// Block (0,0,0) also computes lambda.
__global__ void prep_kernel(const float* __restrict__ v, const float4* __restrict__ k,
                            uint2* __restrict__ kh,
                            const float* __restrict__ lq1, const float* __restrict__ lk1,
                            const float* __restrict__ lq2, const float* __restrict__ lk2) {
    const int tid = threadIdx.x;  // 256 threads

    if (blockIdx.y == 4) {
        // K convert: 512 chunks (x:32, z:16) x 4096 float4 each
        int chunk = blockIdx.z * 32 + blockIdx.x;
        size_t base = (size_t)chunk * 4096;
        #pragma unroll
        for (int i = 0; i < 16; i++) {
            size_t idx = base + tid + i * 256;
            float4 vv = k[idx];
            uint2 o;
            o.x = pack2(vv.x, vv.y);
            o.y = pack2(vv.z, vv.w);
            kh[idx] = o;
        }
        return;
    }

    __shared__ __half st[32][66];
    __shared__ float lr1[4], lr2[4];
    int sbase = blockIdx.x * 64, dbase = blockIdx.y * 32, bh = blockIdx.z;
    const float* src = v + (size_t)bh * S_ * D_;
    __half* dst = g_vth + (size_t)bh * (size_t)D_ * S_;

    #pragma unroll
    for (int i = 0; i < 8; i++) {
        int idx = tid + i * 256;
        int s = idx >> 5, d = idx & 31;
        st[d][s] = __float2half(src[(size_t)(sbase + s) * D_ + dbase + d]);
    }
    __syncthreads();
    #pragma unroll
    for (int i = 0; i < 4; i++) {
        int idx = tid + i * 256;
        int d = idx >> 5, x = idx & 31;
        *(__half2*)(dst + (size_t)(dbase + d) * S_ + sbase + 2 * x) =
            *(const __half2*)&st[d][2 * x];
    }

    if (blockIdx.x == 0 && blockIdx.y == 0 && blockIdx.z == 0) {
        if (tid < 128) {
            float v1 = lq1[tid] * lk1[tid];
            float v2 = lq2[tid] * lk2[tid];
            #pragma unroll
            for (int o = 16; o; o >>= 1) {
                v1 += __shfl_xor_sync(0xffffffffu, v1, o);
                v2 += __shfl_xor_sync(0xffffffffu, v2, o);
            }
            if ((tid & 31) == 0) { lr1[tid >> 5] = v1; lr2[tid >> 5] = v2; }
        }
        __syncthreads();
        if (tid == 0) {
            float a = lr1[0] + lr1[1] + lr1[2] + lr1[3];
            float b = lr2[0] + lr2[1] + lr2[2] + lr2[3];
            g_lam = expf(a) - expf(b) + 0.8f;
        }
    }
}

// ---------------------------------------------------------------------------
// fp16 mma flash attention with ghostmax (R14/R6 configuration, frozen).
// Output stored fp16 to halve epilogue traffic.
// ---------------------------------------------------------------------------
__global__ __launch_bounds__(NT, 1)
void attn_kernel(const float* __restrict__ q) {
    extern __shared__ __half smh[];
    const uint32_t sb = smem_u32(smh);
    const int tid = threadIdx.x, lane = tid & 31, warp = tid >> 5;
    const int g = lane >> 2, t = lane & 3;
    const int qt = (int)gridDim.x - 1 - (int)blockIdx.x;  // heavy tiles first
    const int h2 = blockIdx.y, b = blockIdx.z;
    const int qbase = qt * BQ;
    const int row_lo = qbase + warp * 16 + g;
    const int row_hi = row_lo + 8;
    const int rowmax = qbase + warp * 16 + 15;
    const size_t baseQ  = ((size_t)b * H2_ + h2) * S_ * D_;
    const size_t baseVT = ((size_t)b * H_ + (h2 >> 1)) * (size_t)D_ * S_;
    const float scaling = 0.08838834764831845f;

    const int rowsel = (lane & 7) + ((lane >> 4) << 3);
    const uint32_t koff = ((lane >> 3) & 1) * 16;

    // ---- Q A-fragments: convert from fp32 once into registers
    uint32_t aq[8][4];
    {
        const float* Qlo = q + baseQ + (size_t)row_lo * D_;
        const float* Qhi = q + baseQ + (size_t)row_hi * D_;
        #pragma unroll
        for (int ks = 0; ks < 8; ks++) {
            float2 v0 = *(const float2*)(Qlo + ks * 16 + 2 * t);
            float2 v1 = *(const float2*)(Qhi + ks * 16 + 2 * t);
            float2 v2 = *(const float2*)(Qlo + ks * 16 + 2 * t + 8);
            float2 v3 = *(const float2*)(Qhi + ks * 16 + 2 * t + 8);
            aq[ks][0] = pack2(v0.x * scaling, v0.y * scaling);
            aq[ks][1] = pack2(v1.x * scaling, v1.y * scaling);
            aq[ks][2] = pack2(v2.x * scaling, v2.y * scaling);
            aq[ks][3] = pack2(v3.x * scaling, v3.y * scaling);
        }
    }

    const int nsteps = 2 * (qt + 1);

    auto issue = [&](int jt, int buf) {
        const __half* ksrc = g_kh + baseQ + (size_t)jt * BK * D_;
        uint32_t kdst = sb + (OFF_K + buf * KSTRIDE) * 2;
        #pragma unroll
        for (int i = 0; i < 4; i++) {
            int idx = tid + i * NT;
            int r = idx >> 4, c = idx & 15;
            CP16(kdst + r * 272 + c * 16, ksrc + r * 128 + c * 8);
        }
        const __half* vsrc = g_vth + baseVT + jt * BK;
        uint32_t vdst = sb + (OFF_V + buf * VSTRIDE) * 2;
        #pragma unroll
        for (int i = 0; i < 4; i++) {
            int idx = tid + i * NT;
            int r = idx >> 3, c = idx & 7;
            CP16(vdst + r * 144 + c * 16, vsrc + (size_t)r * S_ + c * 8);
        }
        CP_COMMIT();
    };

    issue(0, 0);

    float o[16][4];
    #pragma unroll
    for (int i = 0; i < 16; i++)
        #pragma unroll
        for (int j = 0; j < 4; j++) o[i][j] = 0.0f;
    float l_lo = 0.0f, l_hi = 0.0f;

    for (int jt = 0; jt < nsteps; ++jt) {
        const int buf = jt & 1;
        __syncthreads();
        if (jt + 1 < nsteps) {
            issue(jt + 1, buf ^ 1);
            CP_WAIT(1);
        } else {
            CP_WAIT(0);
        }
        __syncthreads();

        if (jt * BK <= rowmax) {
            // ---- GEMM1: S = Q @ K^T
            float s[8][4];
            #pragma unroll
            for (int i = 0; i < 8; i++)
                #pragma unroll
                for (int j = 0; j < 4; j++) s[i][j] = 0.0f;

            const uint32_t kmb = sb + (OFF_K + buf * KSTRIDE) * 2 + rowsel * 272 + koff;
            #pragma unroll
            for (int ks = 0; ks < 8; ks++) {
                #pragma unroll
                for (int np = 0; np < 4; np++) {
                    uint32_t b0, b1, b2, b3;
                    LDSM4(b0, b1, b2, b3, kmb + np * (16 * 272) + ks * 32);
                    mma16(s[2 * np],     aq[ks][0], aq[ks][1], aq[ks][2], aq[ks][3], b0, b1);
                    mma16(s[2 * np + 1], aq[ks][0], aq[ks][1], aq[ks][2], aq[ks][3], b2, b3);
                }
            }

            // ---- ghostmax numerators + causal mask + row sums
            #pragma unroll
            for (int nt = 0; nt < 8; nt++) {
                int c0 = jt * BK + nt * 8 + 2 * t;
                float p0 = (c0     <= row_lo) ? __expf(s[nt][0]) : 0.0f;
                float p1 = (c0 + 1 <= row_lo) ? __expf(s[nt][1]) : 0.0f;
                float p2 = (c0     <= row_hi) ? __expf(s[nt][2]) : 0.0f;
                float p3 = (c0 + 1 <= row_hi) ? __expf(s[nt][3]) : 0.0f;
                s[nt][0] = p0; s[nt][1] = p1; s[nt][2] = p2; s[nt][3] = p3;
                l_lo += p0 + p1;
                l_hi += p2 + p3;
            }

            // ---- GEMM2: O += P @ V (C-frags feed A-frags directly)
            const uint32_t vmb = sb + (OFF_V + buf * VSTRIDE) * 2 + rowsel * 144 + koff;
            #pragma unroll
            for (int j2 = 0; j2 < 4; j2++) {
                uint32_t a0 = pack2(s[2 * j2][0],     s[2 * j2][1]);
                uint32_t a1 = pack2(s[2 * j2][2],     s[2 * j2][3]);
                uint32_t a2 = pack2(s[2 * j2 + 1][0], s[2 * j2 + 1][1]);
                uint32_t a3 = pack2(s[2 * j2 + 1][2], s[2 * j2 + 1][3]);
                #pragma unroll
                for (int np = 0; np < 8; np++) {
                    uint32_t b0, b1, b2, b3;
                    LDSM4(b0, b1, b2, b3, vmb + np * (16 * 144) + j2 * 32);
                    mma16(o[2 * np],     a0, a1, a2, a3, b0, b1);
                    mma16(o[2 * np + 1], a0, a1, a2, a3, b2, b3);
                }
            }
        }
    }

    // reduce l across quad, normalize, store fp16
    l_lo += __shfl_xor_sync(0xffffffffu, l_lo, 1);
    l_lo += __shfl_xor_sync(0xffffffffu, l_lo, 2);
    l_hi += __shfl_xor_sync(0xffffffffu, l_hi, 1);
    l_hi += __shfl_xor_sync(0xffffffffu, l_hi, 2);
    const float inv_lo = 1.0f / (l_lo + 1.0f);
    const float inv_hi = 1.0f / (l_hi + 1.0f);

    __half* olo = g_oh + baseQ + (size_t)row_lo * D_;
    __half* ohi = g_oh + baseQ + (size_t)row_hi * D_;
    #pragma unroll
    for (int nt = 0; nt < 16; nt++) {
        int c = nt * 8 + 2 * t;
        *(uint32_t*)(olo + c) = pack2(o[nt][0] * inv_lo, o[nt][1] * inv_lo);
        *(uint32_t*)(ohi + c) = pack2(o[nt][2] * inv_hi, o[nt][3] * inv_hi);
    }
}

// ---------------------------------------------------------------------------
// GroupNorm stats over x = o1 - lam*o2 per (b,h), fp16 input.
// ---------------------------------------------------------------------------
__global__ void gn_partial() {
    const int slice = blockIdx.x;   // 0..63
    const int bh = blockIdx.y;      // 0..15
    const int b = bh >> 3, h = bh & 7;
    const float lam = g_lam;
    const uint4* o1 = (const uint4*)(g_oh + ((size_t)b * H2_ + 2 * h) * S_ * D_);
    const uint4* o2 = o1 + (size_t)S_ * D_ / 8;
    float s = 0.0f, s2 = 0.0f;
    #pragma unroll
    for (int i = 0; i < 2; i++) {
        int idx = slice * 512 + threadIdx.x + i * 256;
        uint4 ua = o1[idx], uc = o2[idx];
        #pragma unroll
        for (int w = 0; w < 4; w++) {
            uint32_t wa = (&ua.x)[w], wc = (&uc.x)[w];
            float2 fa = __half22float2(*(const __half2*)&wa);
            float2 fc = __half22float2(*(const __half2*)&wc);
            float x0 = fa.x - lam * fc.x;
            float x1 = fa.y - lam * fc.y;
            s += x0 + x1;
            s2 = fmaf(x0, x0, s2);
            s2 = fmaf(x1, x1, s2);
        }
    }
    #pragma unroll
    for (int o = 16; o; o >>= 1) {
        s  += __shfl_xor_sync(0xffffffffu, s, o);
        s2 += __shfl_xor_sync(0xffffffffu, s2, o);
    }
    __shared__ double rs[8], rs2[8];
    if ((threadIdx.x & 31) == 0) {
        rs[threadIdx.x >> 5] = (double)s;
        rs2[threadIdx.x >> 5] = (double)s2;
    }
    __syncthreads();
    if (threadIdx.x == 0) {
        double a = 0.0, c = 0.0;
        #pragma unroll
        for (int i = 0; i < 8; i++) { a += rs[i]; c += rs2[i]; }
        g_part[bh * 64 + slice] = make_double2(a, c);
    }
}

// finalize (64-slice reduce of g_part) fused into apply; fp16 input; 512 thr
__global__ void gn_apply(const float* __restrict__ gw, const float* __restrict__ gb,
                         float* __restrict__ out) {
    __shared__ float2 stsh;
    const size_t e0 = (size_t)blockIdx.x * 2048;
    {
        int c_ = (int)((e0 >> 11) & 1023);
        int bh = ((int)(e0 >> 21)) * 8 + (c_ >> 7);
        if (threadIdx.x < 32) {
            double2 p0 = g_part[bh * 64 + threadIdx.x];
            double2 p1 = g_part[bh * 64 + threadIdx.x + 32];
            double s = p0.x + p1.x, s2 = p0.y + p1.y;
            #pragma unroll
            for (int o = 16; o; o >>= 1) {
                s  += __shfl_xor_sync(0xffffffffu, s, o);
                s2 += __shfl_xor_sync(0xffffffffu, s2, o);
            }
            if (threadIdx.x == 0) {
                const double N = (double)S_ * D_;
                double mean = s / N;
                double var = s2 / N - mean * mean;
                stsh = make_float2((float)mean, (float)(1.0 / sqrt(var + 1e-5)));
            }
        }
    }
    __syncthreads();
    float2 st = stsh;
    size_t e = e0 + (size_t)threadIdx.x * 4;
    int t = (int)(e & 2047);
    int c = (int)((e >> 11) & 1023);
    int b = (int)(e >> 21);
    int h = c >> 7, cl = c & 127;
    int s = cl * 16 + (t >> 7), d = t & 127;
    const float lam = g_lam;
    size_t off = (((size_t)b * H2_ + 2 * h) * S_ + s) * D_ + d;
    uint2 ua = *(const uint2*)(g_oh + off);
    uint2 uc = *(const uint2*)(g_oh + off + (size_t)S_ * D_);
    float2 a0 = __half22float2(*(const __half2*)&ua.x);
    float2 a1 = __half22float2(*(const __half2*)&ua.y);
    float2 c0 = __half22float2(*(const __half2*)&uc.x);
    float2 c1 = __half22float2(*(const __half2*)&uc.y);
    float wgt = 0.2f * st.y * gw[c];
    float bias = 0.2f * (gb[c] - st.x * st.y * gw[c]);
    float4 r;
    r.x = (a0.x - lam * c0.x) * wgt + bias;
    r.y = (a0.y - lam * c0.y) * wgt + bias;
    r.z = (a1.x - lam * c1.x) * wgt + bias;
    r.w = (a1.y - lam * c1.y) * wgt + bias;
    *(float4*)(out + e) = r;
}

// ---------------------------------------------------------------------------
extern "C" void kernel_launch(void* const* d_in, const int* in_sizes, int n_in,
                              void* d_out, int out_size) {
    const float* q   = (const float*)d_in[0];
    const float* k   = (const float*)d_in[1];
    const float* v   = (const float*)d_in[2];
    const float* lq1 = (const float*)d_in[3];
    const float* lk1 = (const float*)d_in[4];
    const float* lq2 = (const float*)d_in[5];
    const float* lk2 = (const float*)d_in[6];
    const float* gw  = (const float*)d_in[7];
    const float* gb  = (const float*)d_in[8];
    float* out = (float*)d_out;

    const int smem = SMH * 2;  // 71680 B
    cudaFuncSetAttribute(attn_kernel, cudaFuncAttributeMaxDynamicSharedMemorySize, smem);

    __half* kh; cudaGetSymbolAddress((void**)&kh, g_kh);

    prep_kernel<<<dim3(32, 5, 16), 256>>>(v, (const float4*)k, (uint2*)kh,
                                          lq1, lk1, lq2, lk2);
    attn_kernel<<<dim3(S_ / BQ, H2_, B_), NT, smem>>>(q);
    gn_partial<<<dim3(64, 16), 256>>>();
    gn_apply<<<2048, 512>>>(gw, gb, out);
}